// round 4
// baseline (speedup 1.0000x reference)
#include <cuda_runtime.h>
#include <cuda_bf16.h>

// Problem constants: B=16, N=1024, M=4096, D=64
#define BB 16
#define NN 1024
#define MM 4096
#define DD 64

// ---------------- device scratch (no cudaMalloc allowed) ----------------
__device__ float g_C[(size_t)BB * NN * MM];                 // 256 MB cost matrix
__device__ float g_x2[BB * NN];
__device__ float g_y2[BB * MM];
// packed moves: 4 cells per byte (2 bits each), row stride = MM/4 = 1024 bytes.
// +128 pad: backtrack tile loads may read up to 80B past a row end.
__device__ unsigned char g_mv[(size_t)BB * NN * (MM / 4) + 128];
__device__ int g_j0[BB];

// ---------------- kernel 0: row squared norms ----------------
__global__ void norms_kernel(const float* __restrict__ x, const float* __restrict__ y) {
    int idx = blockIdx.x * blockDim.x + threadIdx.x;
    const float* src;
    float* dst;
    if (idx < BB * NN) {
        src = x + (size_t)idx * DD;
        dst = g_x2 + idx;
    } else if (idx < BB * NN + BB * MM) {
        int k = idx - BB * NN;
        src = y + (size_t)k * DD;
        dst = g_y2 + k;
    } else {
        return;
    }
    float s = 0.f;
#pragma unroll
    for (int q = 0; q < DD / 4; q++) {
        float4 v = *(const float4*)(src + q * 4);
        s += v.x * v.x + v.y * v.y + v.z * v.z + v.w * v.w;
    }
    *dst = s;
}

// ---------------- kernel 1: C = x2 + y2 - 2 * x @ y^T ----------------
// 128x128 tile, 256 threads, 8x8 micro-tile, BK=32 (2 k-steps of D=64).
__global__ void __launch_bounds__(256) gemm_kernel(const float* __restrict__ x,
                                                   const float* __restrict__ y) {
    __shared__ float Xs[32][128];
    __shared__ float Ys[32][128];
    int b = blockIdx.z;
    int i0 = blockIdx.y * 128;
    int j0 = blockIdx.x * 128;
    const float* xb = x + (size_t)b * NN * DD;
    const float* yb = y + (size_t)b * MM * DD;
    int tid = threadIdx.x;
    int txc = tid & 15, tyc = tid >> 4;

    float acc[8][8];
#pragma unroll
    for (int a = 0; a < 8; a++)
#pragma unroll
        for (int c = 0; c < 8; c++) acc[a][c] = 0.f;

#pragma unroll
    for (int kt = 0; kt < DD; kt += 32) {
#pragma unroll
        for (int p = 0; p < 4; p++) {
            int idx = tid + p * 256;     // 0..1023
            int q = idx & 7;             // which float4 in the 32-wide k slab
            int r = idx >> 3;            // tile row 0..127
            float4 xv = *(const float4*)(xb + (size_t)(i0 + r) * DD + kt + q * 4);
            Xs[q * 4 + 0][r] = xv.x;
            Xs[q * 4 + 1][r] = xv.y;
            Xs[q * 4 + 2][r] = xv.z;
            Xs[q * 4 + 3][r] = xv.w;
            float4 yv = *(const float4*)(yb + (size_t)(j0 + r) * DD + kt + q * 4);
            Ys[q * 4 + 0][r] = yv.x;
            Ys[q * 4 + 1][r] = yv.y;
            Ys[q * 4 + 2][r] = yv.z;
            Ys[q * 4 + 3][r] = yv.w;
        }
        __syncthreads();
#pragma unroll
        for (int kk = 0; kk < 32; kk++) {
            float xf[8], yf[8];
            *(float4*)&xf[0] = *(const float4*)&Xs[kk][tyc * 4];
            *(float4*)&xf[4] = *(const float4*)&Xs[kk][64 + tyc * 4];
            *(float4*)&yf[0] = *(const float4*)&Ys[kk][txc * 4];
            *(float4*)&yf[4] = *(const float4*)&Ys[kk][64 + txc * 4];
#pragma unroll
            for (int mm = 0; mm < 8; mm++)
#pragma unroll
                for (int nn = 0; nn < 8; nn++)
                    acc[mm][nn] = fmaf(xf[mm], yf[nn], acc[mm][nn]);
        }
        __syncthreads();
    }

    float y2v[8];
    *(float4*)&y2v[0] = *(const float4*)(g_y2 + b * MM + j0 + txc * 4);
    *(float4*)&y2v[4] = *(const float4*)(g_y2 + b * MM + j0 + 64 + txc * 4);
#pragma unroll
    for (int mm = 0; mm < 8; mm++) {
        int row = i0 + ((mm < 4) ? (tyc * 4 + mm) : (64 + tyc * 4 + mm - 4));
        float x2v = g_x2[b * NN + row];
        float* crow = g_C + ((size_t)b * NN + row) * MM + j0;
        float4 v0, v1;
        v0.x = x2v + y2v[0] - 2.f * acc[mm][0];
        v0.y = x2v + y2v[1] - 2.f * acc[mm][1];
        v0.z = x2v + y2v[2] - 2.f * acc[mm][2];
        v0.w = x2v + y2v[3] - 2.f * acc[mm][3];
        v1.x = x2v + y2v[4] - 2.f * acc[mm][4];
        v1.y = x2v + y2v[5] - 2.f * acc[mm][5];
        v1.z = x2v + y2v[6] - 2.f * acc[mm][6];
        v1.w = x2v + y2v[7] - 2.f * acc[mm][7];
        *(float4*)(crow + txc * 4) = v0;
        *(float4*)(crow + 64 + txc * 4) = v1;
    }
}

// ---------------- kernel 2: subsequence-DTW forward DP ----------------
// One CTA of 1024 threads per batch, 4 columns per thread.
// Row recurrence D[j] = min(a[j], D[j-1] + C[j]) solved with a min-plus scan:
//   element (c, a); combine (s,m) ⊕ (s',m') = (s+s', min(m+s', m'))
// Exclusive-prefix M of thread t == D[i][4t-1] (left neighbor / dl for moves).
__device__ __forceinline__ unsigned mvcode(float dd, float du, float dl) {
    // priority: diagonal, up, left — matches the reference backtrack
    if (dd <= du && dd <= dl) return 0u;
    if (du <= dl) return 1u;
    return 2u;
}

__global__ void __launch_bounds__(1024) dtw_kernel(float* __restrict__ out) {
    int b = blockIdx.x;
    int t = threadIdx.x;
    int lane = t & 31;
    int warp = t >> 5;
    const float* Cb = g_C + (size_t)b * NN * MM;
    unsigned char* mvb = g_mv + (size_t)b * NN * (MM / 4);
    const float INF = __int_as_float(0x7f800000);

    __shared__ float2 sWT[32];
    __shared__ float2 sWP[32];
    __shared__ float sEx[1024];
    __shared__ int sBi[32];

    // row 0: D = C[0,:]
    float4 c4 = *(const float4*)(Cb + (size_t)t * 4);
    float pd0 = c4.x, pd1 = c4.y, pd2 = c4.z, pd3 = c4.w;
    sEx[t] = pd3;
    c4 = *(const float4*)(Cb + (size_t)MM + t * 4);  // prefetch row 1
    __syncthreads();
    float pLeft = (t > 0) ? sEx[t - 1] : INF;

    for (int i = 1; i < NN; i++) {
        float c0 = c4.x, c1 = c4.y, c2 = c4.z, c3 = c4.w;
        if (i < NN - 1) c4 = *(const float4*)(Cb + (size_t)(i + 1) * MM + t * 4);

        float a0 = fminf(pd0, pLeft) + c0;
        float a1 = fminf(pd1, pd0) + c1;
        float a2 = fminf(pd2, pd1) + c2;
        float a3 = fminf(pd3, pd2) + c3;

        // thread-local compose of 4 elements
        float S = c0, Mv = a0;
        S += c1; Mv = fminf(Mv + c1, a1);
        S += c2; Mv = fminf(Mv + c2, a2);
        S += c3; Mv = fminf(Mv + c3, a3);

        // warp inclusive scan (non-commutative, prefix from lower lanes)
        float iS = S, iM = Mv;
#pragma unroll
        for (int off = 1; off < 32; off <<= 1) {
            float oS = __shfl_up_sync(0xffffffffu, iS, off);
            float oM = __shfl_up_sync(0xffffffffu, iM, off);
            if (lane >= off) {
                iM = fminf(oM + iS, iM);
                iS = oS + iS;
            }
        }
        // exclusive within warp
        float eS = __shfl_up_sync(0xffffffffu, iS, 1);
        float eM = __shfl_up_sync(0xffffffffu, iM, 1);
        if (lane == 0) { eS = 0.f; eM = INF; }

        if (lane == 31) sWT[warp] = make_float2(iS, iM);
        __syncthreads();
        if (warp == 0) {
            float2 wv = sWT[lane];
            float wS = wv.x, wM = wv.y;
#pragma unroll
            for (int off = 1; off < 32; off <<= 1) {
                float oS = __shfl_up_sync(0xffffffffu, wS, off);
                float oM = __shfl_up_sync(0xffffffffu, wM, off);
                if (lane >= off) {
                    wM = fminf(oM + wS, wM);
                    wS = oS + wS;
                }
            }
            float pS = __shfl_up_sync(0xffffffffu, wS, 1);
            float pM = __shfl_up_sync(0xffffffffu, wM, 1);
            if (lane == 0) { pS = 0.f; pM = INF; }
            sWP[lane] = make_float2(pS, pM);
        }
        __syncthreads();

        float2 wp = sWP[warp];
        float ExS = wp.x + eS;
        float ExM = fminf(wp.y + eS, eM);   // == D[i][4t-1]

        // finalize this thread's 4 D values
        float Sr = ExS, Mr = ExM;
        Sr += c0; Mr = fminf(Mr + c0, a0); float nd0 = Mr;
        Sr += c1; Mr = fminf(Mr + c1, a1); float nd1 = Mr;
        Sr += c2; Mr = fminf(Mr + c2, a2); float nd2 = Mr;
        Sr += c3; Mr = fminf(Mr + c3, a3); float nd3 = Mr;

        // move codes (dd = Dprev[j-1], du = Dprev[j], dl = D[i][j-1])
        unsigned m0 = mvcode(pLeft, pd0, ExM);
        unsigned m1 = mvcode(pd0, pd1, nd0);
        unsigned m2 = mvcode(pd1, pd2, nd1);
        unsigned m3 = mvcode(pd2, pd3, nd2);
        mvb[(size_t)i * (MM / 4) + t] =
            (unsigned char)(m0 | (m1 << 2) | (m2 << 4) | (m3 << 6));

        pLeft = ExM;
        pd0 = nd0; pd1 = nd1; pd2 = nd2; pd3 = nd3;
    }

    // argmin of last row (first index on exact ties, like jnp.argmin)
    float bv = pd0; int bi = 4 * t;
    if (pd1 < bv) { bv = pd1; bi = 4 * t + 1; }
    if (pd2 < bv) { bv = pd2; bi = 4 * t + 2; }
    if (pd3 < bv) { bv = pd3; bi = 4 * t + 3; }
#pragma unroll
    for (int off = 16; off > 0; off >>= 1) {
        float ov = __shfl_down_sync(0xffffffffu, bv, off);
        int oi = __shfl_down_sync(0xffffffffu, bi, off);
        if (ov < bv || (ov == bv && oi < bi)) { bv = ov; bi = oi; }
    }
    if (lane == 0) { sEx[warp] = bv; sBi[warp] = bi; }
    __syncthreads();
    if (warp == 0) {
        bv = sEx[lane];
        bi = sBi[lane];
#pragma unroll
        for (int off = 16; off > 0; off >>= 1) {
            float ov = __shfl_down_sync(0xffffffffu, bv, off);
            int oi = __shfl_down_sync(0xffffffffu, bi, off);
            if (ov < bv || (ov == bv && oi < bi)) { bv = ov; bi = oi; }
        }
        if (lane == 0) {
            out[b] = bv;      // dtw_cost
            g_j0[b] = bi;
        }
    }
}

// ---------------- kernel 3: backtrack over packed moves ----------------
// One warp per batch. Walks a 64-row x 320-col (80-byte) smem-cached tile of
// the packed move matrix; >=63 steps guaranteed per tile reload.
__global__ void __launch_bounds__(32) backtrack_kernel(const float* __restrict__ xt,
                                                       const float* __restrict__ yt,
                                                       float* __restrict__ out) {
    int b = blockIdx.x;
    int lane = threadIdx.x;
    __shared__ uint4 tile4[64][5];    // 64 rows x 80 bytes
    __shared__ int syl[NN];
    __shared__ int sij[2];
    unsigned char* tileb = (unsigned char*)tile4;
    const unsigned char* mvb = g_mv + (size_t)b * NN * (MM / 4);

    int i = NN - 1;
    int j = g_j0[b];
    if (lane == 0) syl[NN - 1] = j;
    __syncwarp();

    while (i > 0) {
        int r0 = i - 63; if (r0 < 1) r0 = 1;
        int cb = j >> 2;
        int cb0 = cb - 63; if (cb0 < 0) cb0 = 0;
        cb0 &= ~15;  // 16B-align for uint4 loads
        // cooperative tile load: rows r0..r0+63, byte cols cb0..cb0+79
#pragma unroll
        for (int p = 0; p < 10; p++) {
            int idx = lane + p * 32;           // 0..319
            int r = idx / 5, q = idx - r * 5;
            tile4[r][q] = *(const uint4*)(mvb + (size_t)(r0 + r) * (MM / 4) + cb0 + q * 16);
        }
        __syncwarp();
        if (lane == 0) {
            while (i > 0 && i >= r0 && (j >> 2) >= cb0) {
                unsigned byt = tileb[(i - r0) * 80 + ((j >> 2) - cb0)];
                unsigned mv = (byt >> ((j & 3) * 2)) & 3u;
                if (mv == 0u) { i--; j--; syl[i] = j; }
                else if (mv == 1u) { i--; syl[i] = j; }
                else { j--; }
            }
            sij[0] = i;
            sij[1] = j;
        }
        __syncwarp();
        i = sij[0];
        j = sij[1];
        __syncwarp();
    }

    // write w_ts (= x_t) and w_vs (= y_t gathered at per-row max path column)
    for (int n = lane; n < NN; n += 32) {
        out[BB + b * NN + n] = xt[b * NN + n];
        out[BB + BB * NN + b * NN + n] = yt[(size_t)b * MM + syl[n]];
    }
}

// ---------------- launch ----------------
extern "C" void kernel_launch(void* const* d_in, const int* in_sizes, int n_in,
                              void* d_out, int out_size) {
    const float* x = (const float*)d_in[0];   // [16,1024,64]
    const float* y = (const float*)d_in[1];   // [16,4096,64]
    const float* xt = (const float*)d_in[2];  // [16,1024]
    const float* yt = (const float*)d_in[3];  // [16,4096]
    float* out = (float*)d_out;               // [16] cost, [16,1024] w_ts, [16,1024] w_vs

    int totalRows = BB * NN + BB * MM;
    norms_kernel<<<(totalRows + 255) / 256, 256>>>(x, y);

    dim3 gg(MM / 128, NN / 128, BB);
    gemm_kernel<<<gg, 256>>>(x, y);

    dtw_kernel<<<BB, 1024>>>(out);

    backtrack_kernel<<<BB, 32>>>(xt, yt, out);
}